// round 15
// baseline (speedup 1.0000x reference)
#include <cuda_runtime.h>
#include <cuda_fp16.h>
#include <math.h>
#include <stdint.h>

#define NT 2048
#define DD 1024
#define CC 768
#define NH 16
#define HD 64
#define MT 2048
#define FF 4096

typedef unsigned short ushortx;

// ---------------- scratch (fp16 stored as ushort) -----------------------------
__device__ ushortx g_xq[NT * DD];
__device__ ushortx g_kv[MT * CC];
__device__ ushortx g_q[NT * DD];
__device__ ushortx g_k[MT * DD];
__device__ ushortx g_v[MT * DD];
__device__ ushortx g_o[NT * DD];
__device__ float   g_x1[NT * DD];
__device__ ushortx g_hln[NT * DD];
__device__ ushortx g_h1[(size_t)NT * FF];
__device__ ushortx g_wq[DD * DD];
__device__ ushortx g_wk[CC * DD];
__device__ ushortx g_wv[CC * DD];
__device__ ushortx g_wo[DD * DD];
__device__ ushortx g_w1[(size_t)DD * FF];
__device__ ushortx g_w2[(size_t)FF * DD];

// ---------------- helpers ----------------------------------------------------
__device__ __forceinline__ uint32_t smem_addr_u32(const void* p) {
    uint32_t a;
    asm("{ .reg .u64 t; cvta.to.shared.u64 t, %1; cvt.u32.u64 %0, t; }" : "=r"(a) : "l"(p));
    return a;
}
__device__ __forceinline__ void ldsm4(uint32_t* r, uint32_t addr) {
    asm volatile("ldmatrix.sync.aligned.m8n8.x4.shared.b16 {%0,%1,%2,%3}, [%4];"
                 : "=r"(r[0]), "=r"(r[1]), "=r"(r[2]), "=r"(r[3]) : "r"(addr));
}
__device__ __forceinline__ void ldsm4t(uint32_t* r, uint32_t addr) {
    asm volatile("ldmatrix.sync.aligned.m8n8.x4.trans.shared.b16 {%0,%1,%2,%3}, [%4];"
                 : "=r"(r[0]), "=r"(r[1]), "=r"(r[2]), "=r"(r[3]) : "r"(addr));
}
__device__ __forceinline__ void mma_f16(float* d, const uint32_t* a, const uint32_t* b) {
    asm volatile(
        "mma.sync.aligned.m16n8k16.row.col.f32.f16.f16.f32 "
        "{%0,%1,%2,%3}, {%4,%5,%6,%7}, {%8,%9}, {%0,%1,%2,%3};"
        : "+f"(d[0]), "+f"(d[1]), "+f"(d[2]), "+f"(d[3])
        : "r"(a[0]), "r"(a[1]), "r"(a[2]), "r"(a[3]), "r"(b[0]), "r"(b[1]));
}
__device__ __forceinline__ uint32_t packh2(float x, float y) {
    __half2 h = __floats2half2_rn(x, y);
    return *(uint32_t*)&h;
}
__device__ __forceinline__ void cpa16(uint32_t d, const void* g) {
    asm volatile("cp.async.cg.shared.global [%0], [%1], 16;" :: "r"(d), "l"(g));
}
__device__ __forceinline__ void cpcommit() { asm volatile("cp.async.commit_group;" ::: "memory"); }
template <int N>
__device__ __forceinline__ void cpwait() {
    asm volatile("cp.async.wait_group %0;" :: "n"(N) : "memory");
}

// ---------------- block reduce -------------------------------------------------
__device__ __forceinline__ float block_reduce_sum(float v) {
    __shared__ float sh[8];
    int tid = threadIdx.x;
#pragma unroll
    for (int o = 16; o > 0; o >>= 1) v += __shfl_down_sync(0xffffffffu, v, o);
    if ((tid & 31) == 0) sh[tid >> 5] = v;
    __syncthreads();
    if (tid < 32) {
        v = (tid < 8) ? sh[tid] : 0.f;
#pragma unroll
        for (int o = 4; o > 0; o >>= 1) v += __shfl_down_sync(0xffffffffu, v, o);
        if (tid == 0) sh[0] = v;
    }
    __syncthreads();
    float r = sh[0];
    __syncthreads();
    return r;
}

// ---------------- LN row body (256 threads) ------------------------------------
template <int DIM>
__device__ __forceinline__ void ln_body(
    const float* __restrict__ xr, const float* __restrict__ w,
    const float* __restrict__ b, ushortx* __restrict__ orow) {
    int tid = threadIdx.x;
    float4 f = make_float4(0.f, 0.f, 0.f, 0.f);
    if (tid < DIM / 4) f = ((const float4*)xr)[tid];
    float s = f.x + f.y + f.z + f.w;
    float mean = block_reduce_sum(s) * (1.f / DIM);
    float vv = 0.f;
    if (tid < DIM / 4) {
        float c0 = f.x - mean, c1 = f.y - mean, c2 = f.z - mean, c3 = f.w - mean;
        vv = c0 * c0 + c1 * c1 + c2 * c2 + c3 * c3;
    }
    float var = block_reduce_sum(vv) * (1.f / DIM);
    float inv = rsqrtf(var + 1e-12f);
    if (tid < DIM / 4) {
        float4 w4 = ((const float4*)w)[tid];
        float4 b4 = ((const float4*)b)[tid];
        float o0 = (f.x - mean) * inv * w4.x + b4.x;
        float o1 = (f.y - mean) * inv * w4.y + b4.y;
        float o2 = (f.z - mean) * inv * w4.z + b4.z;
        float o3 = (f.w - mean) * inv * w4.w + b4.w;
        ((uint2*)orow)[tid] = make_uint2(packh2(o0, o1), packh2(o2, o3));
    }
}

template <int DIM>
__global__ __launch_bounds__(256) void ln_half_kernel(
    const float* __restrict__ x, const float* __restrict__ w, const float* __restrict__ b,
    ushortx* __restrict__ oh) {
    ln_body<DIM>(x + (size_t)blockIdx.x * DIM, w, b, oh + (size_t)blockIdx.x * DIM);
}

// ---------------- fused prologue: 2 LNs + 6 weight converts --------------------
#define CV_WQ (DD * DD / 4)
#define CV_WK (CC * DD / 4)
#define CV_TOT (2 * CV_WQ + 2 * CV_WK + 2 * (DD * FF / 4))
#define CV_BLOCKS ((CV_TOT + 255) / 256)

__global__ __launch_bounds__(256) void prologue_kernel(
    const float* __restrict__ x, const float* __restrict__ qn_w,
    const float* __restrict__ qn_b, ushortx* __restrict__ xq,
    const float* __restrict__ ctx, const float* __restrict__ kvn_w,
    const float* __restrict__ kvn_b, ushortx* __restrict__ kv,
    const float* __restrict__ wq, ushortx* __restrict__ wqp,
    const float* __restrict__ wk, ushortx* __restrict__ wkp,
    const float* __restrict__ wv, ushortx* __restrict__ wvp,
    const float* __restrict__ wo, ushortx* __restrict__ wop,
    const float* __restrict__ w1, ushortx* __restrict__ w1p,
    const float* __restrict__ w2, ushortx* __restrict__ w2p) {
    int b = blockIdx.x;
    if (b < NT) {
        ln_body<DD>(x + (size_t)b * DD, qn_w, qn_b, xq + (size_t)b * DD);
        return;
    }
    if (b < NT + MT) {
        int r = b - NT;
        ln_body<CC>(ctx + (size_t)r * CC, kvn_w, kvn_b, kv + (size_t)r * CC);
        return;
    }
    int i = (b - NT - MT) * 256 + threadIdx.x;
    if (i >= CV_TOT) return;
    const float* s;
    ushortx* d;
    if (i < CV_WQ) { s = wq; d = wqp; }
    else if (i < CV_WQ + CV_WK) { s = wk; d = wkp; i -= CV_WQ; }
    else if (i < CV_WQ + 2 * CV_WK) { s = wv; d = wvp; i -= CV_WQ + CV_WK; }
    else if (i < 2 * CV_WQ + 2 * CV_WK) { s = wo; d = wop; i -= CV_WQ + 2 * CV_WK; }
    else if (i < 2 * CV_WQ + 2 * CV_WK + DD * FF / 4) {
        s = w1; d = w1p; i -= 2 * CV_WQ + 2 * CV_WK;
    } else { s = w2; d = w2p; i -= 2 * CV_WQ + 2 * CV_WK + DD * FF / 4; }
    float4 f = ((const float4*)s)[i];
    ((uint2*)d)[i] = make_uint2(packh2(f.x, f.y), packh2(f.z, f.w));
}

// ---------------- fp16 GEMM core (128 thr, 4 warps, 3-stage, 3 CTAs/SM) --------
template <int BM_, int BIAS, int RES, int GELU, int OUTH>
__device__ __forceinline__ void gemm_core(
    const ushortx* __restrict__ A, const ushortx* __restrict__ B,
    const float* __restrict__ bias, const float* __restrict__ Res,
    float* __restrict__ Cf, ushortx* __restrict__ Ch,
    int K, int lda, int ldb, int bx, int by) {
    constexpr int RA = 80, RB = 272;
    constexpr int ASZ = BM_ * RA;
    constexpr int BSZ = 32 * RB;
    constexpr int STAGE = ASZ + BSZ;
    constexpr int MI = BM_ / 32;
    constexpr int ACH = BM_ * 4 / 128;

    extern __shared__ char sm[];
    const int tid = threadIdx.x, lane = tid & 31, wid = tid >> 5;
    const int wm = wid & 1, wn = wid >> 1;
    const uint32_t sb = smem_addr_u32(sm);

    const ushortx* Ab = A + (size_t)by * BM_ * lda;
    const ushortx* Bb = B + (size_t)bx * 128;

    auto issue = [&](int k0, int buf) {
        uint32_t d = sb + buf * STAGE;
#pragma unroll
        for (int j = 0; j < ACH; j++) {
            int i = tid + j * 128;
            int r = i >> 2, s = i & 3;
            cpa16(d + (uint32_t)(r * RA + s * 16), Ab + (size_t)r * lda + k0 + s * 8);
        }
#pragma unroll
        for (int j = 0; j < 4; j++) {
            int i = tid + j * 128;
            int kr = i >> 4, s = i & 15;
            cpa16(d + ASZ + (uint32_t)(kr * RB + s * 16),
                  Bb + (size_t)(k0 + kr) * ldb + s * 8);
        }
        cpcommit();
    };

    float acc[MI][8][4];
#pragma unroll
    for (int i = 0; i < MI; i++)
#pragma unroll
        for (int j = 0; j < 8; j++)
#pragma unroll
            for (int q = 0; q < 4; q++) acc[i][j][q] = 0.f;

    const int lr = lane & 15;
    const int ac8 = (lane >> 4) << 3;

    auto domma = [&](int buf) {
        const uint32_t ab = sb + buf * STAGE;
        const uint32_t bb = ab + ASZ;
#pragma unroll
        for (int kk = 0; kk < 2; kk++) {
            uint32_t bf[4][4];
#pragma unroll
            for (int nj = 0; nj < 4; nj++) {
                uint32_t boff = (uint32_t)(kk * 16 + lr) * RB +
                                (uint32_t)(wn * 64 + nj * 16 + ac8) * 2;
                ldsm4t(bf[nj], bb + boff);
            }
#pragma unroll
            for (int mi = 0; mi < MI; mi++) {
                uint32_t aoff = (uint32_t)(wm * (BM_ / 2) + mi * 16 + lr) * RA +
                                (uint32_t)(kk * 16 + ac8) * 2;
                uint32_t af[4];
                ldsm4(af, ab + aoff);
#pragma unroll
                for (int nj = 0; nj < 4; nj++) {
                    mma_f16(acc[mi][2 * nj], af, &bf[nj][0]);
                    mma_f16(acc[mi][2 * nj + 1], af, &bf[nj][2]);
                }
            }
        }
    };

    // 3-stage ring (R7-verified pattern): issue 0,1; wait<1>; issue t+2 at (t+2)%3
    const int T = K >> 5;
    issue(0, 0);
    issue(32, 1);
#pragma unroll 1
    for (int t = 0; t < T; t++) {
        if (t < T - 1) cpwait<1>();
        else cpwait<0>();
        __syncthreads();
        if (t + 2 < T) {
            int b2 = t + 2;
            issue(b2 * 32, b2 - (b2 / 3) * 3);
        }
        domma(t - (t / 3) * 3);
    }

    // epilogue
    const int g = lane >> 2, q = lane & 3;
    const size_t c0 = (size_t)by * BM_ * ldb + (size_t)bx * 128;
#pragma unroll
    for (int mi = 0; mi < MI; mi++)
#pragma unroll
        for (int nj = 0; nj < 8; nj++) {
            int col = wn * 64 + nj * 8 + q * 2;
            float bv0 = BIAS ? bias[bx * 128 + col] : 0.f;
            float bv1 = BIAS ? bias[bx * 128 + col + 1] : 0.f;
#pragma unroll
            for (int rr = 0; rr < 2; rr++) {
                int row = wm * (BM_ / 2) + mi * 16 + g + rr * 8;
                float v0 = acc[mi][nj][rr * 2] + bv0;
                float v1 = acc[mi][nj][rr * 2 + 1] + bv1;
                if (RES) {
                    const float* rp = Res + c0 + (size_t)row * ldb + col;
                    v0 += rp[0];
                    v1 += rp[1];
                }
                if (GELU) {
                    float i0 = 0.7978845608028654f * (v0 + 0.044715f * v0 * v0 * v0);
                    v0 = 0.5f * v0 * (1.f + tanhf(i0));
                    float i1 = 0.7978845608028654f * (v1 + 0.044715f * v1 * v1 * v1);
                    v1 = 0.5f * v1 * (1.f + tanhf(i1));
                }
                if (OUTH) {
                    *(uint32_t*)(Ch + c0 + (size_t)row * ldb + col) = packh2(v0, v1);
                } else {
                    *(float2*)(Cf + c0 + (size_t)row * ldb + col) = make_float2(v0, v1);
                }
            }
        }
}

template <int BM_, int BIAS, int RES, int GELU, int OUTH>
__global__ __launch_bounds__(128, 3) void half_gemm(
    const ushortx* A, const ushortx* B, const float* bias, const float* Res,
    float* Cf, ushortx* Ch, int K, int lda, int ldb) {
    gemm_core<BM_, BIAS, RES, GELU, OUTH>(A, B, bias, Res, Cf, Ch, K, lda, ldb,
                                          blockIdx.x, blockIdx.y);
}

// fused QKV
__global__ __launch_bounds__(128, 3) void qkv_gemm(
    const ushortx* xq, const ushortx* kv,
    const ushortx* wq, const ushortx* wk, const ushortx* wv,
    const float* bq, const float* bk, const float* bv,
    ushortx* q, ushortx* k, ushortx* v) {
    int z = blockIdx.z;
    const ushortx *A, *B;
    const float* bias;
    ushortx* C;
    int K, lda;
    if (z == 0) { A = xq; B = wq; bias = bq; C = q; K = DD; lda = DD; }
    else if (z == 1) { A = kv; B = wk; bias = bk; C = k; K = CC; lda = CC; }
    else { A = kv; B = wv; bias = bv; C = v; K = CC; lda = CC; }
    gemm_core<128, 1, 0, 0, 1>(A, B, bias, nullptr, nullptr, C, K, lda, DD,
                               blockIdx.x, blockIdx.y);
}

// ---------------- flash attention (128 thr, 4 warps x 32 query rows) -----------
__global__ __launch_bounds__(128, 2) void flash_kernel(
    const ushortx* __restrict__ Q, const ushortx* __restrict__ K,
    const ushortx* __restrict__ V, ushortx* __restrict__ O) {
    constexpr int R = 144;
    constexpr int QO = 0;
    constexpr int KVB0 = 18432, KVSZ = 18432;
    constexpr int NKB = MT / 64;

    extern __shared__ char sm[];
    const int tid = threadIdx.x, lane = tid & 31, wid = tid >> 5;
    const int h = blockIdx.y, qb = blockIdx.x;
    const uint32_t sb = smem_addr_u32(sm);

    const ushortx* Qg = Q + (size_t)qb * 128 * DD + h * HD;
    const ushortx* Kg = K + h * HD;
    const ushortx* Vg = V + h * HD;

#pragma unroll
    for (int j = 0; j < 8; j++) {
        int i = tid + j * 128;
        int r = i >> 3, s = i & 7;
        cpa16(sb + QO + (uint32_t)(r * R + s * 16), Qg + (size_t)r * DD + s * 8);
    }
    auto issueKV = [&](int kb, int buf) {
        uint32_t base = sb + KVB0 + (uint32_t)buf * KVSZ;
#pragma unroll
        for (int j = 0; j < 4; j++) {
            int i = tid + j * 128;
            int r = i >> 3, s = i & 7;
            uint32_t dd = base + (uint32_t)(r * R + s * 16);
            size_t so = (size_t)(kb * 64 + r) * DD + s * 8;
            cpa16(dd, Kg + so);
            cpa16(dd + 9216, Vg + so);
        }
        cpcommit();
    };
    issueKV(0, 0);
    issueKV(1, 1);

    float o[2][8][4];
#pragma unroll
    for (int mt = 0; mt < 2; mt++)
#pragma unroll
        for (int j = 0; j < 8; j++)
#pragma unroll
            for (int q = 0; q < 4; q++) o[mt][j][q] = 0.f;
    float m[2][2] = {{-INFINITY, -INFINITY}, {-INFINITY, -INFINITY}};
    float l[2][2] = {{0.f, 0.f}, {0.f, 0.f}};

    const int lr = lane & 15;
    const int ac8 = (lane >> 4) << 3;
    const int bn = (lane & 7) + ((lane >> 4) << 3);
    const int bc8 = ((lane >> 3) & 1) << 3;

    for (int kb = 0; kb < NKB; kb++) {
        if (kb < NKB - 1) cpwait<1>();
        else cpwait<0>();
        __syncthreads();
        const uint32_t KVB = sb + KVB0 + (uint32_t)(kb & 1) * KVSZ;

        float s[2][8][4];
#pragma unroll
        for (int mt = 0; mt < 2; mt++)
#pragma unroll
            for (int j = 0; j < 8; j++)
#pragma unroll
                for (int q = 0; q < 4; q++) s[mt][j][q] = 0.f;

#pragma unroll
        for (int kf = 0; kf < 4; kf++) {
            uint32_t qf[2][4], kfr[4][4];
#pragma unroll
            for (int mt = 0; mt < 2; mt++)
                ldsm4(qf[mt], sb + QO + (uint32_t)(wid * 32 + mt * 16 + lr) * R +
                                  (uint32_t)(kf * 16 + ac8) * 2);
#pragma unroll
            for (int nb = 0; nb < 4; nb++)
                ldsm4(kfr[nb], KVB + (uint32_t)(nb * 16 + bn) * R +
                                   (uint32_t)(kf * 16 + bc8) * 2);
#pragma unroll
            for (int mt = 0; mt < 2; mt++)
#pragma unroll
                for (int nb = 0; nb < 4; nb++) {
                    mma_f16(s[mt][2 * nb], qf[mt], &kfr[nb][0]);
                    mma_f16(s[mt][2 * nb + 1], qf[mt], &kfr[nb][2]);
                }
        }

#pragma unroll
        for (int mt = 0; mt < 2; mt++) {
            float mx0 = -INFINITY, mx1 = -INFINITY;
#pragma unroll
            for (int j = 0; j < 8; j++) {
                mx0 = fmaxf(mx0, fmaxf(s[mt][j][0], s[mt][j][1]));
                mx1 = fmaxf(mx1, fmaxf(s[mt][j][2], s[mt][j][3]));
            }
            mx0 = fmaxf(mx0, __shfl_xor_sync(0xffffffffu, mx0, 1));
            mx0 = fmaxf(mx0, __shfl_xor_sync(0xffffffffu, mx0, 2));
            mx1 = fmaxf(mx1, __shfl_xor_sync(0xffffffffu, mx1, 1));
            mx1 = fmaxf(mx1, __shfl_xor_sync(0xffffffffu, mx1, 2));
            float m0n = fmaxf(m[mt][0], mx0), m1n = fmaxf(m[mt][1], mx1);
            float sc0 = __expf((m[mt][0] - m0n) * 0.125f);
            float sc1 = __expf((m[mt][1] - m1n) * 0.125f);
            m[mt][0] = m0n;
            m[mt][1] = m1n;
            float su0 = 0.f, su1 = 0.f;
#pragma unroll
            for (int j = 0; j < 8; j++) {
                s[mt][j][0] = __expf((s[mt][j][0] - m0n) * 0.125f);
                s[mt][j][1] = __expf((s[mt][j][1] - m0n) * 0.125f);
                s[mt][j][2] = __expf((s[mt][j][2] - m1n) * 0.125f);
                s[mt][j][3] = __expf((s[mt][j][3] - m1n) * 0.125f);
                su0 += s[mt][j][0] + s[mt][j][1];
                su1 += s[mt][j][2] + s[mt][j][3];
            }
            su0 += __shfl_xor_sync(0xffffffffu, su0, 1);
            su0 += __shfl_xor_sync(0xffffffffu, su0, 2);
            su1 += __shfl_xor_sync(0xffffffffu, su1, 1);
            su1 += __shfl_xor_sync(0xffffffffu, su1, 2);
            l[mt][0] = l[mt][0] * sc0 + su0;
            l[mt][1] = l[mt][1] * sc1 + su1;
#pragma unroll
            for (int j = 0; j < 8; j++) {
                o[mt][j][0] *= sc0;
                o[mt][j][1] *= sc0;
                o[mt][j][2] *= sc1;
                o[mt][j][3] *= sc1;
            }
        }

#pragma unroll
        for (int kf = 0; kf < 4; kf++) {
            uint32_t ph[2][4], vf[4][4];
#pragma unroll
            for (int mt = 0; mt < 2; mt++) {
                ph[mt][0] = packh2(s[mt][2 * kf][0], s[mt][2 * kf][1]);
                ph[mt][1] = packh2(s[mt][2 * kf][2], s[mt][2 * kf][3]);
                ph[mt][2] = packh2(s[mt][2 * kf + 1][0], s[mt][2 * kf + 1][1]);
                ph[mt][3] = packh2(s[mt][2 * kf + 1][2], s[mt][2 * kf + 1][3]);
            }
#pragma unroll
            for (int nb = 0; nb < 4; nb++)
                ldsm4t(vf[nb], KVB + 9216 + (uint32_t)(kf * 16 + lr) * R +
                                   (uint32_t)(nb * 16 + ac8) * 2);
#pragma unroll
            for (int mt = 0; mt < 2; mt++)
#pragma unroll
                for (int nb = 0; nb < 4; nb++) {
                    mma_f16(o[mt][2 * nb], ph[mt], &vf[nb][0]);
                    mma_f16(o[mt][2 * nb + 1], ph[mt], &vf[nb][2]);
                }
        }
        __syncthreads();
        if (kb + 2 < NKB) issueKV(kb + 2, kb & 1);
    }

    const int g = lane >> 2, q = lane & 3;
#pragma unroll
    for (int mt = 0; mt < 2; mt++) {
        float i0 = 1.f / l[mt][0], i1 = 1.f / l[mt][1];
        size_t base = (size_t)(qb * 128 + wid * 32 + mt * 16) * DD + h * HD;
#pragma unroll
        for (int nj = 0; nj < 8; nj++) {
            int col = nj * 8 + q * 2;
            *(uint32_t*)(O + base + (size_t)g * DD + col) =
                packh2(o[mt][nj][0] * i0, o[mt][nj][1] * i0);
            *(uint32_t*)(O + base + (size_t)(g + 8) * DD + col) =
                packh2(o[mt][nj][2] * i1, o[mt][nj][3] * i1);
        }
    }
}

// ---------------- launch -----------------------------------------------------
extern "C" void kernel_launch(void* const* d_in, const int* in_sizes, int n_in,
                              void* d_out, int out_size) {
    const float* x     = (const float*)d_in[0];
    const float* ctx   = (const float*)d_in[1];
    const float* wq    = (const float*)d_in[2];
    const float* bq    = (const float*)d_in[3];
    const float* wk    = (const float*)d_in[4];
    const float* bk    = (const float*)d_in[5];
    const float* wv    = (const float*)d_in[6];
    const float* bv    = (const float*)d_in[7];
    const float* wo    = (const float*)d_in[8];
    const float* bo    = (const float*)d_in[9];
    const float* w1    = (const float*)d_in[10];
    const float* b1    = (const float*)d_in[11];
    const float* w2    = (const float*)d_in[12];
    const float* b2    = (const float*)d_in[13];
    const float* qn_w  = (const float*)d_in[14];
    const float* qn_b  = (const float*)d_in[15];
    const float* kvn_w = (const float*)d_in[16];
    const float* kvn_b = (const float*)d_in[17];
    const float* pn_w  = (const float*)d_in[18];
    const float* pn_b  = (const float*)d_in[19];
    float* out = (float*)d_out;

#define GETP(name) \
    ushortx* name##p; cudaGetSymbolAddress((void**)&name##p, g_##name)
    GETP(xq); GETP(kv); GETP(q); GETP(k); GETP(v); GETP(o); GETP(hln); GETP(h1);
    GETP(wq); GETP(wk); GETP(wv); GETP(wo); GETP(w1); GETP(w2);
#undef GETP
    float* x1;
    cudaGetSymbolAddress((void**)&x1, g_x1);

    const int GSM128 = 3 * (128 * 80 + 32 * 272);  // 56832
    const int GSM64  = 3 * (64 * 80 + 32 * 272);   // 41472
    const int FSM = 18432 + 2 * 18432;             // 55296
    cudaFuncSetAttribute((const void*)qkv_gemm,
                         cudaFuncAttributeMaxDynamicSharedMemorySize, GSM128);
    cudaFuncSetAttribute((const void*)half_gemm<64, 1, 1, 0, 0>,
                         cudaFuncAttributeMaxDynamicSharedMemorySize, GSM64);
    cudaFuncSetAttribute((const void*)half_gemm<128, 1, 0, 1, 1>,
                         cudaFuncAttributeMaxDynamicSharedMemorySize, GSM128);
    cudaFuncSetAttribute((const void*)flash_kernel,
                         cudaFuncAttributeMaxDynamicSharedMemorySize, FSM);

    // 0+1. fused prologue
    prologue_kernel<<<NT + MT + CV_BLOCKS, 256>>>(
        x, qn_w, qn_b, xqp, ctx, kvn_w, kvn_b, kvp,
        wq, wqp, wk, wkp, wv, wvp, wo, wop, w1, w1p, w2, w2p);

    // 2. fused Q/K/V projections
    qkv_gemm<<<dim3(DD / 128, NT / 128, 3), 128, GSM128>>>(
        xqp, kvp, wqp, wkp, wvp, bq, bk, bv, qp, kp, vp);

    // 3. fused attention
    flash_kernel<<<dim3(NT / 128, NH), 128, FSM>>>(qp, kp, vp, op);

    // 4. x1 = o @ wo + bo + x
    half_gemm<64, 1, 1, 0, 0><<<dim3(DD / 128, NT / 64), 128, GSM64>>>(
        op, wop, bo, x, x1, nullptr, DD, DD, DD);

    // 5. MLP
    ln_half_kernel<DD><<<NT, 256>>>(x1, pn_w, pn_b, hlnp);
    half_gemm<128, 1, 0, 1, 1><<<dim3(FF / 128, NT / 128), 128, GSM128>>>(
        hlnp, w1p, b1, nullptr, nullptr, h1p, DD, DD, FF);
    half_gemm<64, 1, 1, 0, 0><<<dim3(DD / 128, NT / 64), 128, GSM64>>>(
        h1p, w2p, b2, x1, out, nullptr, FF, FF, DD);
}

// round 16
// speedup vs baseline: 1.0180x; 1.0180x over previous
#include <cuda_runtime.h>
#include <cuda_fp16.h>
#include <math.h>
#include <stdint.h>

#define NT 2048
#define DD 1024
#define CC 768
#define NH 16
#define HD 64
#define MT 2048
#define FF 4096

typedef unsigned short ushortx;

// ---------------- scratch (fp16 stored as ushort) -----------------------------
__device__ ushortx g_xq[NT * DD];
__device__ ushortx g_kv[MT * CC];
__device__ ushortx g_q[NT * DD];
__device__ ushortx g_k[MT * DD];
__device__ ushortx g_v[MT * DD];
__device__ ushortx g_o[NT * DD];
__device__ float   g_x1[NT * DD];
__device__ ushortx g_hln[NT * DD];
__device__ ushortx g_h1[(size_t)NT * FF];
__device__ ushortx g_wq[DD * DD];
__device__ ushortx g_wk[CC * DD];
__device__ ushortx g_wv[CC * DD];
__device__ ushortx g_wo[DD * DD];
__device__ ushortx g_w1[(size_t)DD * FF];
__device__ ushortx g_w2[(size_t)FF * DD];

// ---------------- helpers ----------------------------------------------------
__device__ __forceinline__ uint32_t smem_addr_u32(const void* p) {
    uint32_t a;
    asm("{ .reg .u64 t; cvta.to.shared.u64 t, %1; cvt.u32.u64 %0, t; }" : "=r"(a) : "l"(p));
    return a;
}
__device__ __forceinline__ void ldsm4(uint32_t* r, uint32_t addr) {
    asm volatile("ldmatrix.sync.aligned.m8n8.x4.shared.b16 {%0,%1,%2,%3}, [%4];"
                 : "=r"(r[0]), "=r"(r[1]), "=r"(r[2]), "=r"(r[3]) : "r"(addr));
}
__device__ __forceinline__ void ldsm4t(uint32_t* r, uint32_t addr) {
    asm volatile("ldmatrix.sync.aligned.m8n8.x4.trans.shared.b16 {%0,%1,%2,%3}, [%4];"
                 : "=r"(r[0]), "=r"(r[1]), "=r"(r[2]), "=r"(r[3]) : "r"(addr));
}
__device__ __forceinline__ void mma_f16(float* d, const uint32_t* a, const uint32_t* b) {
    asm volatile(
        "mma.sync.aligned.m16n8k16.row.col.f32.f16.f16.f32 "
        "{%0,%1,%2,%3}, {%4,%5,%6,%7}, {%8,%9}, {%0,%1,%2,%3};"
        : "+f"(d[0]), "+f"(d[1]), "+f"(d[2]), "+f"(d[3])
        : "r"(a[0]), "r"(a[1]), "r"(a[2]), "r"(a[3]), "r"(b[0]), "r"(b[1]));
}
__device__ __forceinline__ uint32_t packh2(float x, float y) {
    __half2 h = __floats2half2_rn(x, y);
    return *(uint32_t*)&h;
}
__device__ __forceinline__ void cpa16(uint32_t d, const void* g) {
    asm volatile("cp.async.cg.shared.global [%0], [%1], 16;" :: "r"(d), "l"(g));
}
__device__ __forceinline__ void cpcommit() { asm volatile("cp.async.commit_group;" ::: "memory"); }
template <int N>
__device__ __forceinline__ void cpwait() {
    asm volatile("cp.async.wait_group %0;" :: "n"(N) : "memory");
}

// ---------------- block reduce -------------------------------------------------
__device__ __forceinline__ float block_reduce_sum(float v) {
    __shared__ float sh[8];
    int tid = threadIdx.x;
#pragma unroll
    for (int o = 16; o > 0; o >>= 1) v += __shfl_down_sync(0xffffffffu, v, o);
    if ((tid & 31) == 0) sh[tid >> 5] = v;
    __syncthreads();
    if (tid < 32) {
        v = (tid < 8) ? sh[tid] : 0.f;
#pragma unroll
        for (int o = 4; o > 0; o >>= 1) v += __shfl_down_sync(0xffffffffu, v, o);
        if (tid == 0) sh[0] = v;
    }
    __syncthreads();
    float r = sh[0];
    __syncthreads();
    return r;
}

// ---------------- LN row body (256 threads) ------------------------------------
template <int DIM>
__device__ __forceinline__ void ln_body(
    const float* __restrict__ xr, const float* __restrict__ w,
    const float* __restrict__ b, ushortx* __restrict__ orow) {
    int tid = threadIdx.x;
    float4 f = make_float4(0.f, 0.f, 0.f, 0.f);
    if (tid < DIM / 4) f = ((const float4*)xr)[tid];
    float s = f.x + f.y + f.z + f.w;
    float mean = block_reduce_sum(s) * (1.f / DIM);
    float vv = 0.f;
    if (tid < DIM / 4) {
        float c0 = f.x - mean, c1 = f.y - mean, c2 = f.z - mean, c3 = f.w - mean;
        vv = c0 * c0 + c1 * c1 + c2 * c2 + c3 * c3;
    }
    float var = block_reduce_sum(vv) * (1.f / DIM);
    float inv = rsqrtf(var + 1e-12f);
    if (tid < DIM / 4) {
        float4 w4 = ((const float4*)w)[tid];
        float4 b4 = ((const float4*)b)[tid];
        float o0 = (f.x - mean) * inv * w4.x + b4.x;
        float o1 = (f.y - mean) * inv * w4.y + b4.y;
        float o2 = (f.z - mean) * inv * w4.z + b4.z;
        float o3 = (f.w - mean) * inv * w4.w + b4.w;
        ((uint2*)orow)[tid] = make_uint2(packh2(o0, o1), packh2(o2, o3));
    }
}

template <int DIM>
__global__ __launch_bounds__(256) void ln_half_kernel(
    const float* __restrict__ x, const float* __restrict__ w, const float* __restrict__ b,
    ushortx* __restrict__ oh) {
    ln_body<DIM>(x + (size_t)blockIdx.x * DIM, w, b, oh + (size_t)blockIdx.x * DIM);
}

// ---------------- fused prologue: 2 LNs + 6 weight converts --------------------
#define CV_WQ (DD * DD / 4)
#define CV_WK (CC * DD / 4)
#define CV_TOT (2 * CV_WQ + 2 * CV_WK + 2 * (DD * FF / 4))
#define CV_BLOCKS ((CV_TOT + 255) / 256)

__global__ __launch_bounds__(256) void prologue_kernel(
    const float* __restrict__ x, const float* __restrict__ qn_w,
    const float* __restrict__ qn_b, ushortx* __restrict__ xq,
    const float* __restrict__ ctx, const float* __restrict__ kvn_w,
    const float* __restrict__ kvn_b, ushortx* __restrict__ kv,
    const float* __restrict__ wq, ushortx* __restrict__ wqp,
    const float* __restrict__ wk, ushortx* __restrict__ wkp,
    const float* __restrict__ wv, ushortx* __restrict__ wvp,
    const float* __restrict__ wo, ushortx* __restrict__ wop,
    const float* __restrict__ w1, ushortx* __restrict__ w1p,
    const float* __restrict__ w2, ushortx* __restrict__ w2p) {
    int b = blockIdx.x;
    if (b < NT) {
        ln_body<DD>(x + (size_t)b * DD, qn_w, qn_b, xq + (size_t)b * DD);
        return;
    }
    if (b < NT + MT) {
        int r = b - NT;
        ln_body<CC>(ctx + (size_t)r * CC, kvn_w, kvn_b, kv + (size_t)r * CC);
        return;
    }
    int i = (b - NT - MT) * 256 + threadIdx.x;
    if (i >= CV_TOT) return;
    const float* s;
    ushortx* d;
    if (i < CV_WQ) { s = wq; d = wqp; }
    else if (i < CV_WQ + CV_WK) { s = wk; d = wkp; i -= CV_WQ; }
    else if (i < CV_WQ + 2 * CV_WK) { s = wv; d = wvp; i -= CV_WQ + CV_WK; }
    else if (i < 2 * CV_WQ + 2 * CV_WK) { s = wo; d = wop; i -= CV_WQ + 2 * CV_WK; }
    else if (i < 2 * CV_WQ + 2 * CV_WK + DD * FF / 4) {
        s = w1; d = w1p; i -= 2 * CV_WQ + 2 * CV_WK;
    } else { s = w2; d = w2p; i -= 2 * CV_WQ + 2 * CV_WK + DD * FF / 4; }
    float4 f = ((const float4*)s)[i];
    ((uint2*)d)[i] = make_uint2(packh2(f.x, f.y), packh2(f.z, f.w));
}

// ---------------- fp16 GEMM core (128 thr, 4 warps, 4-stage ring) --------------
template <int BM_, int BIAS, int RES, int GELU, int OUTH>
__device__ __forceinline__ void gemm_core(
    const ushortx* __restrict__ A, const ushortx* __restrict__ B,
    const float* __restrict__ bias, const float* __restrict__ Res,
    float* __restrict__ Cf, ushortx* __restrict__ Ch,
    int K, int lda, int ldb, int bx, int by) {
    constexpr int RA = 80, RB = 272;
    constexpr int ASZ = BM_ * RA;
    constexpr int BSZ = 32 * RB;
    constexpr int STAGE = ASZ + BSZ;
    constexpr int MI = BM_ / 32;
    constexpr int ACH = BM_ * 4 / 128;

    extern __shared__ char sm[];
    const int tid = threadIdx.x, lane = tid & 31, wid = tid >> 5;
    const int wm = wid & 1, wn = wid >> 1;
    const uint32_t sb = smem_addr_u32(sm);

    const ushortx* Ab = A + (size_t)by * BM_ * lda;
    const ushortx* Bb = B + (size_t)bx * 128;

    auto issue = [&](int k0, int buf) {
        uint32_t d = sb + buf * STAGE;
#pragma unroll
        for (int j = 0; j < ACH; j++) {
            int i = tid + j * 128;
            int r = i >> 2, s = i & 3;
            cpa16(d + (uint32_t)(r * RA + s * 16), Ab + (size_t)r * lda + k0 + s * 8);
        }
#pragma unroll
        for (int j = 0; j < 4; j++) {
            int i = tid + j * 128;
            int kr = i >> 4, s = i & 15;
            cpa16(d + ASZ + (uint32_t)(kr * RB + s * 16),
                  Bb + (size_t)(k0 + kr) * ldb + s * 8);
        }
        cpcommit();
    };

    float acc[MI][8][4];
#pragma unroll
    for (int i = 0; i < MI; i++)
#pragma unroll
        for (int j = 0; j < 8; j++)
#pragma unroll
            for (int q = 0; q < 4; q++) acc[i][j][q] = 0.f;

    const int lr = lane & 15;
    const int ac8 = (lane >> 4) << 3;

    auto domma = [&](int buf) {
        const uint32_t ab = sb + buf * STAGE;
        const uint32_t bb = ab + ASZ;
#pragma unroll
        for (int kk = 0; kk < 2; kk++) {
            uint32_t bf[4][4];
#pragma unroll
            for (int nj = 0; nj < 4; nj++) {
                uint32_t boff = (uint32_t)(kk * 16 + lr) * RB +
                                (uint32_t)(wn * 64 + nj * 16 + ac8) * 2;
                ldsm4t(bf[nj], bb + boff);
            }
#pragma unroll
            for (int mi = 0; mi < MI; mi++) {
                uint32_t aoff = (uint32_t)(wm * (BM_ / 2) + mi * 16 + lr) * RA +
                                (uint32_t)(kk * 16 + ac8) * 2;
                uint32_t af[4];
                ldsm4(af, ab + aoff);
#pragma unroll
                for (int nj = 0; nj < 4; nj++) {
                    mma_f16(acc[mi][2 * nj], af, &bf[nj][0]);
                    mma_f16(acc[mi][2 * nj + 1], af, &bf[nj][2]);
                }
            }
        }
    };

    const int T = K >> 5;
    issue(0, 0);
    issue(32, 1);
    issue(64, 2);
#pragma unroll 1
    for (int t = 0; t < T; t++) {
        if (t + 3 <= T) cpwait<2>();
        else if (t + 2 <= T) cpwait<1>();
        else cpwait<0>();
        __syncthreads();
        if (t + 3 < T) issue((t + 3) * 32, (t + 3) & 3);
        domma(t & 3);
    }

    // epilogue
    const int g = lane >> 2, q = lane & 3;
    const size_t c0 = (size_t)by * BM_ * ldb + (size_t)bx * 128;
#pragma unroll
    for (int mi = 0; mi < MI; mi++)
#pragma unroll
        for (int nj = 0; nj < 8; nj++) {
            int col = wn * 64 + nj * 8 + q * 2;
            float bv0 = BIAS ? bias[bx * 128 + col] : 0.f;
            float bv1 = BIAS ? bias[bx * 128 + col + 1] : 0.f;
#pragma unroll
            for (int rr = 0; rr < 2; rr++) {
                int row = wm * (BM_ / 2) + mi * 16 + g + rr * 8;
                float v0 = acc[mi][nj][rr * 2] + bv0;
                float v1 = acc[mi][nj][rr * 2 + 1] + bv1;
                if (RES) {
                    const float* rp = Res + c0 + (size_t)row * ldb + col;
                    v0 += rp[0];
                    v1 += rp[1];
                }
                if (GELU) {
                    float i0 = 0.7978845608028654f * (v0 + 0.044715f * v0 * v0 * v0);
                    v0 = 0.5f * v0 * (1.f + tanhf(i0));
                    float i1 = 0.7978845608028654f * (v1 + 0.044715f * v1 * v1 * v1);
                    v1 = 0.5f * v1 * (1.f + tanhf(i1));
                }
                if (OUTH) {
                    *(uint32_t*)(Ch + c0 + (size_t)row * ldb + col) = packh2(v0, v1);
                } else {
                    *(float2*)(Cf + c0 + (size_t)row * ldb + col) = make_float2(v0, v1);
                }
            }
        }
}

template <int BM_, int BIAS, int RES, int GELU, int OUTH>
__global__ __launch_bounds__(128, 3) void half_gemm(
    const ushortx* A, const ushortx* B, const float* bias, const float* Res,
    float* Cf, ushortx* Ch, int K, int lda, int ldb) {
    gemm_core<BM_, BIAS, RES, GELU, OUTH>(A, B, bias, Res, Cf, Ch, K, lda, ldb,
                                          blockIdx.x, blockIdx.y);
}

// fused QKV
__global__ __launch_bounds__(128, 3) void qkv_gemm(
    const ushortx* xq, const ushortx* kv,
    const ushortx* wq, const ushortx* wk, const ushortx* wv,
    const float* bq, const float* bk, const float* bv,
    ushortx* q, ushortx* k, ushortx* v) {
    int z = blockIdx.z;
    const ushortx *A, *B;
    const float* bias;
    ushortx* C;
    int K, lda;
    if (z == 0) { A = xq; B = wq; bias = bq; C = q; K = DD; lda = DD; }
    else if (z == 1) { A = kv; B = wk; bias = bk; C = k; K = CC; lda = CC; }
    else { A = kv; B = wv; bias = bv; C = v; K = CC; lda = CC; }
    gemm_core<128, 1, 0, 0, 1>(A, B, bias, nullptr, nullptr, C, K, lda, DD,
                               blockIdx.x, blockIdx.y);
}

// ---------------- flash attention (128 thr, 4 warps x 32 query rows) -----------
__global__ __launch_bounds__(128, 2) void flash_kernel(
    const ushortx* __restrict__ Q, const ushortx* __restrict__ K,
    const ushortx* __restrict__ V, ushortx* __restrict__ O) {
    constexpr int R = 144;
    constexpr int QO = 0;
    constexpr int KVB0 = 18432, KVSZ = 18432;
    constexpr int NKB = MT / 64;

    extern __shared__ char sm[];
    const int tid = threadIdx.x, lane = tid & 31, wid = tid >> 5;
    const int h = blockIdx.y, qb = blockIdx.x;
    const uint32_t sb = smem_addr_u32(sm);

    const ushortx* Qg = Q + (size_t)qb * 128 * DD + h * HD;
    const ushortx* Kg = K + h * HD;
    const ushortx* Vg = V + h * HD;

#pragma unroll
    for (int j = 0; j < 8; j++) {
        int i = tid + j * 128;
        int r = i >> 3, s = i & 7;
        cpa16(sb + QO + (uint32_t)(r * R + s * 16), Qg + (size_t)r * DD + s * 8);
    }
    auto issueKV = [&](int kb, int buf) {
        uint32_t base = sb + KVB0 + (uint32_t)buf * KVSZ;
#pragma unroll
        for (int j = 0; j < 4; j++) {
            int i = tid + j * 128;
            int r = i >> 3, s = i & 7;
            uint32_t dd = base + (uint32_t)(r * R + s * 16);
            size_t so = (size_t)(kb * 64 + r) * DD + s * 8;
            cpa16(dd, Kg + so);
            cpa16(dd + 9216, Vg + so);
        }
        cpcommit();
    };
    issueKV(0, 0);
    issueKV(1, 1);

    float o[2][8][4];
#pragma unroll
    for (int mt = 0; mt < 2; mt++)
#pragma unroll
        for (int j = 0; j < 8; j++)
#pragma unroll
            for (int q = 0; q < 4; q++) o[mt][j][q] = 0.f;
    float m[2][2] = {{-INFINITY, -INFINITY}, {-INFINITY, -INFINITY}};
    float l[2][2] = {{0.f, 0.f}, {0.f, 0.f}};

    const int lr = lane & 15;
    const int ac8 = (lane >> 4) << 3;
    const int bn = (lane & 7) + ((lane >> 4) << 3);
    const int bc8 = ((lane >> 3) & 1) << 3;

    for (int kb = 0; kb < NKB; kb++) {
        if (kb < NKB - 1) cpwait<1>();
        else cpwait<0>();
        __syncthreads();
        const uint32_t KVB = sb + KVB0 + (uint32_t)(kb & 1) * KVSZ;

        float s[2][8][4];
#pragma unroll
        for (int mt = 0; mt < 2; mt++)
#pragma unroll
            for (int j = 0; j < 8; j++)
#pragma unroll
                for (int q = 0; q < 4; q++) s[mt][j][q] = 0.f;

#pragma unroll
        for (int kf = 0; kf < 4; kf++) {
            uint32_t qf[2][4], kfr[4][4];
#pragma unroll
            for (int mt = 0; mt < 2; mt++)
                ldsm4(qf[mt], sb + QO + (uint32_t)(wid * 32 + mt * 16 + lr) * R +
                                  (uint32_t)(kf * 16 + ac8) * 2);
#pragma unroll
            for (int nb = 0; nb < 4; nb++)
                ldsm4(kfr[nb], KVB + (uint32_t)(nb * 16 + bn) * R +
                                   (uint32_t)(kf * 16 + bc8) * 2);
#pragma unroll
            for (int mt = 0; mt < 2; mt++)
#pragma unroll
                for (int nb = 0; nb < 4; nb++) {
                    mma_f16(s[mt][2 * nb], qf[mt], &kfr[nb][0]);
                    mma_f16(s[mt][2 * nb + 1], qf[mt], &kfr[nb][2]);
                }
        }

#pragma unroll
        for (int mt = 0; mt < 2; mt++) {
            float mx0 = -INFINITY, mx1 = -INFINITY;
#pragma unroll
            for (int j = 0; j < 8; j++) {
                mx0 = fmaxf(mx0, fmaxf(s[mt][j][0], s[mt][j][1]));
                mx1 = fmaxf(mx1, fmaxf(s[mt][j][2], s[mt][j][3]));
            }
            mx0 = fmaxf(mx0, __shfl_xor_sync(0xffffffffu, mx0, 1));
            mx0 = fmaxf(mx0, __shfl_xor_sync(0xffffffffu, mx0, 2));
            mx1 = fmaxf(mx1, __shfl_xor_sync(0xffffffffu, mx1, 1));
            mx1 = fmaxf(mx1, __shfl_xor_sync(0xffffffffu, mx1, 2));
            float m0n = fmaxf(m[mt][0], mx0), m1n = fmaxf(m[mt][1], mx1);
            float sc0 = __expf((m[mt][0] - m0n) * 0.125f);
            float sc1 = __expf((m[mt][1] - m1n) * 0.125f);
            m[mt][0] = m0n;
            m[mt][1] = m1n;
            float su0 = 0.f, su1 = 0.f;
#pragma unroll
            for (int j = 0; j < 8; j++) {
                s[mt][j][0] = __expf((s[mt][j][0] - m0n) * 0.125f);
                s[mt][j][1] = __expf((s[mt][j][1] - m0n) * 0.125f);
                s[mt][j][2] = __expf((s[mt][j][2] - m1n) * 0.125f);
                s[mt][j][3] = __expf((s[mt][j][3] - m1n) * 0.125f);
                su0 += s[mt][j][0] + s[mt][j][1];
                su1 += s[mt][j][2] + s[mt][j][3];
            }
            su0 += __shfl_xor_sync(0xffffffffu, su0, 1);
            su0 += __shfl_xor_sync(0xffffffffu, su0, 2);
            su1 += __shfl_xor_sync(0xffffffffu, su1, 1);
            su1 += __shfl_xor_sync(0xffffffffu, su1, 2);
            l[mt][0] = l[mt][0] * sc0 + su0;
            l[mt][1] = l[mt][1] * sc1 + su1;
#pragma unroll
            for (int j = 0; j < 8; j++) {
                o[mt][j][0] *= sc0;
                o[mt][j][1] *= sc0;
                o[mt][j][2] *= sc1;
                o[mt][j][3] *= sc1;
            }
        }

#pragma unroll
        for (int kf = 0; kf < 4; kf++) {
            uint32_t ph[2][4], vf[4][4];
#pragma unroll
            for (int mt = 0; mt < 2; mt++) {
                ph[mt][0] = packh2(s[mt][2 * kf][0], s[mt][2 * kf][1]);
                ph[mt][1] = packh2(s[mt][2 * kf][2], s[mt][2 * kf][3]);
                ph[mt][2] = packh2(s[mt][2 * kf + 1][0], s[mt][2 * kf + 1][1]);
                ph[mt][3] = packh2(s[mt][2 * kf + 1][2], s[mt][2 * kf + 1][3]);
            }
#pragma unroll
            for (int nb = 0; nb < 4; nb++)
                ldsm4t(vf[nb], KVB + 9216 + (uint32_t)(kf * 16 + lr) * R +
                                   (uint32_t)(nb * 16 + ac8) * 2);
#pragma unroll
            for (int mt = 0; mt < 2; mt++)
#pragma unroll
                for (int nb = 0; nb < 4; nb++) {
                    mma_f16(o[mt][2 * nb], ph[mt], &vf[nb][0]);
                    mma_f16(o[mt][2 * nb + 1], ph[mt], &vf[nb][2]);
                }
        }
        __syncthreads();
        if (kb + 2 < NKB) issueKV(kb + 2, kb & 1);
    }

    const int g = lane >> 2, q = lane & 3;
#pragma unroll
    for (int mt = 0; mt < 2; mt++) {
        float i0 = 1.f / l[mt][0], i1 = 1.f / l[mt][1];
        size_t base = (size_t)(qb * 128 + wid * 32 + mt * 16) * DD + h * HD;
#pragma unroll
        for (int nj = 0; nj < 8; nj++) {
            int col = nj * 8 + q * 2;
            *(uint32_t*)(O + base + (size_t)g * DD + col) =
                packh2(o[mt][nj][0] * i0, o[mt][nj][1] * i0);
            *(uint32_t*)(O + base + (size_t)(g + 8) * DD + col) =
                packh2(o[mt][nj][2] * i1, o[mt][nj][3] * i1);
        }
    }
}

// ---------------- launch -----------------------------------------------------
extern "C" void kernel_launch(void* const* d_in, const int* in_sizes, int n_in,
                              void* d_out, int out_size) {
    const float* x     = (const float*)d_in[0];
    const float* ctx   = (const float*)d_in[1];
    const float* wq    = (const float*)d_in[2];
    const float* bq    = (const float*)d_in[3];
    const float* wk    = (const float*)d_in[4];
    const float* bk    = (const float*)d_in[5];
    const float* wv    = (const float*)d_in[6];
    const float* bv    = (const float*)d_in[7];
    const float* wo    = (const float*)d_in[8];
    const float* bo    = (const float*)d_in[9];
    const float* w1    = (const float*)d_in[10];
    const float* b1    = (const float*)d_in[11];
    const float* w2    = (const float*)d_in[12];
    const float* b2    = (const float*)d_in[13];
    const float* qn_w  = (const float*)d_in[14];
    const float* qn_b  = (const float*)d_in[15];
    const float* kvn_w = (const float*)d_in[16];
    const float* kvn_b = (const float*)d_in[17];
    const float* pn_w  = (const float*)d_in[18];
    const float* pn_b  = (const float*)d_in[19];
    float* out = (float*)d_out;

#define GETP(name) \
    ushortx* name##p; cudaGetSymbolAddress((void**)&name##p, g_##name)
    GETP(xq); GETP(kv); GETP(q); GETP(k); GETP(v); GETP(o); GETP(hln); GETP(h1);
    GETP(wq); GETP(wk); GETP(wv); GETP(wo); GETP(w1); GETP(w2);
#undef GETP
    float* x1;
    cudaGetSymbolAddress((void**)&x1, g_x1);

    const int GSM128 = 4 * (128 * 80 + 32 * 272);  // 75776
    const int GSM64  = 4 * (64 * 80 + 32 * 272);   // 55296
    const int FSM = 18432 + 2 * 18432;             // 55296
    cudaFuncSetAttribute((const void*)qkv_gemm,
                         cudaFuncAttributeMaxDynamicSharedMemorySize, GSM128);
    cudaFuncSetAttribute((const void*)half_gemm<64, 1, 1, 0, 0>,
                         cudaFuncAttributeMaxDynamicSharedMemorySize, GSM64);
    cudaFuncSetAttribute((const void*)half_gemm<128, 1, 0, 1, 1>,
                         cudaFuncAttributeMaxDynamicSharedMemorySize, GSM128);
    cudaFuncSetAttribute((const void*)flash_kernel,
                         cudaFuncAttributeMaxDynamicSharedMemorySize, FSM);

    // 0+1. fused prologue
    prologue_kernel<<<NT + MT + CV_BLOCKS, 256>>>(
        x, qn_w, qn_b, xqp, ctx, kvn_w, kvn_b, kvp,
        wq, wqp, wk, wkp, wv, wvp, wo, wop, w1, w1p, w2, w2p);

    // 2. fused Q/K/V projections
    qkv_gemm<<<dim3(DD / 128, NT / 128, 3), 128, GSM128>>>(
        xqp, kvp, wqp, wkp, wvp, bq, bk, bv, qp, kp, vp);

    // 3. fused attention
    flash_kernel<<<dim3(NT / 128, NH), 128, FSM>>>(qp, kp, vp, op);

    // 4. x1 = o @ wo + bo + x
    half_gemm<64, 1, 1, 0, 0><<<dim3(DD / 128, NT / 64), 128, GSM64>>>(
        op, wop, bo, x, x1, nullptr, DD, DD, DD);

    // 5. MLP
    ln_half_kernel<DD><<<NT, 256>>>(x1, pn_w, pn_b, hlnp);
    half_gemm<128, 1, 0, 1, 1><<<dim3(FF / 128, NT / 128), 128, GSM128>>>(
        hlnp, w1p, b1, nullptr, nullptr, h1p, DD, DD, FF);
    half_gemm<64, 1, 1, 0, 0><<<dim3(DD / 128, NT / 64), 128, GSM64>>>(
        h1p, w2p, b2, x1, out, nullptr, FF, FF, DD);
}